// round 2
// baseline (speedup 1.0000x reference)
#include <cuda_runtime.h>
#include <cuda_bf16.h>

// Problem constants
#define NB 8192   // batch
#define ND 1024   // feature dim
#define NC 256    // concept dim
#define MARGIN 0.2f
#define THRESH 0.5f

// ---------------- device scratch (static: no allocations allowed) ----------------
__device__ __nv_bfloat16 g_sim[(size_t)NB * NB];   // 128 MB sim matrix (bf16)
__device__ unsigned g_posbits[NB * (NB / 32)];     // 8 MB positive-pair bitmask
__device__ unsigned g_rowmax[NB];                  // encoded-float per-row max over negatives
__device__ unsigned g_rowflags[NB];                // bit0 = has_pos, bit1 = has_neg
__device__ double   g_sum;
__device__ unsigned g_cnt;

// monotone encode/decode so unsigned atomicMax == float max (handles negatives)
__device__ __forceinline__ unsigned encf(float f) {
    unsigned u = __float_as_uint(f);
    return (u & 0x80000000u) ? ~u : (u | 0x80000000u);
}
__device__ __forceinline__ float decf(unsigned u) {
    u = (u & 0x80000000u) ? (u & 0x7fffffffu) : ~u;
    return __uint_as_float(u);
}

// ---------------- reset (graph replays must start clean) ----------------
__global__ void reset_kernel() {
    int idx = blockIdx.x * 256 + threadIdx.x;      // grid covers NB*(NB/32) = 2,097,152
    if (idx < NB * (NB / 32)) g_posbits[idx] = 0u;
    if (idx < NB) { g_rowmax[idx] = 0u; g_rowflags[idx] = 0u; }
    if (idx == 0) { g_sum = 0.0; g_cnt = 0u; }
}

// ---------------- tiled dual-GEMM + fused mask/rowmax pass ----------------
// 128x128 tile per block, 256 threads, 8x8 microtile per thread.
__device__ __forceinline__ void mm_tiles(const float* __restrict__ A,
                                         const float* __restrict__ Bm,
                                         int ti, int tj, int K,
                                         float (*As)[132], float (*Bs)[132],
                                         float acc[8][8], int tid, int tx, int ty) {
    const int r  = tid >> 1;          // 0..127 : tile row loaded by this thread
    const int kq = (tid & 1) << 2;    // 0 or 4 : k-quad within BK=8
    for (int k0 = 0; k0 < K; k0 += 8) {
        float4 va = *reinterpret_cast<const float4*>(A  + (size_t)(ti + r) * K + k0 + kq);
        float4 vb = *reinterpret_cast<const float4*>(Bm + (size_t)(tj + r) * K + k0 + kq);
        __syncthreads();
        As[kq + 0][r] = va.x; As[kq + 1][r] = va.y; As[kq + 2][r] = va.z; As[kq + 3][r] = va.w;
        Bs[kq + 0][r] = vb.x; Bs[kq + 1][r] = vb.y; Bs[kq + 2][r] = vb.z; Bs[kq + 3][r] = vb.w;
        __syncthreads();
#pragma unroll
        for (int k = 0; k < 8; k++) {
            float a[8], b[8];
#pragma unroll
            for (int q = 0; q < 8; q++) a[q] = As[k][ty * 8 + q];
#pragma unroll
            for (int q = 0; q < 8; q++) b[q] = Bs[k][tx * 8 + q];
#pragma unroll
            for (int i2 = 0; i2 < 8; i2++)
#pragma unroll
                for (int j2 = 0; j2 < 8; j2++)
                    acc[i2][j2] = fmaf(a[i2], b[j2], acc[i2][j2]);
        }
    }
}

__global__ __launch_bounds__(256, 2)
void tile_kernel(const float* __restrict__ img,
                 const float* __restrict__ txt,
                 const float* __restrict__ lab) {
    __shared__ float As[8][132];
    __shared__ float Bs[8][132];
    const int tid = threadIdx.x;
    const int tx = tid & 15, ty = tid >> 4;
    const int ti = blockIdx.y * 128, tj = blockIdx.x * 128;

    float acc[8][8];
#pragma unroll
    for (int i = 0; i < 8; i++)
#pragma unroll
        for (int j = 0; j < 8; j++) acc[i][j] = 0.f;

    // ---- gram = lab @ lab^T (K = 256) : derive masks ----
    mm_tiles(lab, lab, ti, tj, NC, As, Bs, acc, tid, tx, ty);

    unsigned posm[8], negm[8];
#pragma unroll
    for (int ri = 0; ri < 8; ri++) {
        int gi = ti + ty * 8 + ri;
        unsigned pb = 0u, nb = 0u;
#pragma unroll
        for (int rj = 0; rj < 8; rj++) {
            int gj = tj + tx * 8 + rj;
            bool dg = (gi == gj);
            if (!dg) {
                if (acc[ri][rj] > THRESH) pb |= (1u << rj);
                else                      nb |= (1u << rj);
            }
        }
        posm[ri] = pb; negm[ri] = nb;
        if (pb)
            atomicOr(&g_posbits[gi * (NB / 32) + ((tj + tx * 8) >> 5)],
                     pb << ((tx & 3) * 8));
    }

    // ---- sim = img @ txt^T (K = 1024) ----
#pragma unroll
    for (int i = 0; i < 8; i++)
#pragma unroll
        for (int j = 0; j < 8; j++) acc[i][j] = 0.f;
    mm_tiles(img, txt, ti, tj, ND, As, Bs, acc, tid, tx, ty);

    // ---- epilogue: store sim (bf16), per-row max-over-negatives + flags ----
#pragma unroll
    for (int ri = 0; ri < 8; ri++) {
        int gi  = ti + ty * 8 + ri;
        int gj0 = tj + tx * 8;

        // pack 8 fp32 -> 8 bf16 (16 bytes, one uint4 store)
        union { uint4 v; __nv_bfloat162 h[4]; } pk;
#pragma unroll
        for (int q = 0; q < 4; q++)
            pk.h[q] = __floats2bfloat162_rn(acc[ri][2 * q], acc[ri][2 * q + 1]);
        *reinterpret_cast<uint4*>(g_sim + (size_t)gi * NB + gj0) = pk.v;

        float mx = -__int_as_float(0x7f800000);    // -inf
        unsigned nb = negm[ri];
#pragma unroll
        for (int rj = 0; rj < 8; rj++)
            if ((nb >> rj) & 1u) mx = fmaxf(mx, acc[ri][rj]);
        unsigned fl = (posm[ri] ? 1u : 0u) | (nb ? 2u : 0u);

        // reduce across the 16 threads (tx) covering this row: half-warp shuffles
#pragma unroll
        for (int off = 8; off; off >>= 1) {
            float omx = __shfl_xor_sync(0xffffffffu, mx, off, 16);
            mx = fmaxf(mx, omx);
            fl |= __shfl_xor_sync(0xffffffffu, fl, off, 16);
        }
        if (tx == 0) {
            if (fl) atomicOr(&g_rowflags[gi], fl);
            atomicMax(&g_rowmax[gi], encf(mx));
        }
    }
}

// ---------------- pass 2: hinge sum over positive pairs ----------------
__global__ void pass2_kernel() {
    int w = blockIdx.x * 256 + threadIdx.x;        // one 32-col mask word per thread
    double   lsum = 0.0;
    unsigned lcnt = 0u;
    int i  = w >> 8;
    int jb = (w & 255) << 5;
    if (g_rowflags[i] == 3u) {                     // valid = has_pos & has_neg
        unsigned m = g_posbits[w];
        if (m) {
            lcnt = (unsigned)__popc(m);
            float base = MARGIN + decf(g_rowmax[i]);
            const __nv_bfloat16* row = g_sim + (size_t)i * NB + jb;
            float fs = 0.f;
            do {
                int b = __ffs(m) - 1; m &= m - 1u;
                float h = base - __bfloat162float(row[b]);
                if (h > 0.f) fs += h;
            } while (m);
            lsum = (double)fs;
        }
    }
    // warp reduce
#pragma unroll
    for (int off = 16; off; off >>= 1) {
        lsum += __shfl_down_sync(0xffffffffu, lsum, off);
        lcnt += __shfl_down_sync(0xffffffffu, lcnt, off);
    }
    __shared__ double   ssum[8];
    __shared__ unsigned scnt[8];
    int lane = threadIdx.x & 31, wid = threadIdx.x >> 5;
    if (lane == 0) { ssum[wid] = lsum; scnt[wid] = lcnt; }
    __syncthreads();
    if (wid == 0) {
        lsum = (lane < 8) ? ssum[lane] : 0.0;
        lcnt = (lane < 8) ? scnt[lane] : 0u;
#pragma unroll
        for (int off = 4; off; off >>= 1) {
            lsum += __shfl_down_sync(0xffffffffu, lsum, off);
            lcnt += __shfl_down_sync(0xffffffffu, lcnt, off);
        }
        if (lane == 0) {
            atomicAdd(&g_sum, lsum);
            atomicAdd(&g_cnt, lcnt);
        }
    }
}

__global__ void finalize_kernel(float* out) {
    if (threadIdx.x == 0)
        out[0] = (g_cnt > 0u) ? (float)(g_sum / (double)g_cnt) : 0.f;
}

// ---------------- launch ----------------
extern "C" void kernel_launch(void* const* d_in, const int* in_sizes, int n_in,
                              void* d_out, int out_size) {
    const float* img = (const float*)d_in[0];   // [8192,1024]
    const float* txt = (const float*)d_in[1];   // [8192,1024]
    const float* lab = (const float*)d_in[2];   // [8192,256]
    (void)in_sizes; (void)n_in; (void)out_size;

    reset_kernel<<<NB * (NB / 32) / 256, 256>>>();          // 8192 blocks
    dim3 grid(NB / 128, NB / 128);                           // 64 x 64 tiles
    tile_kernel<<<grid, 256>>>(img, txt, lab);
    pass2_kernel<<<NB * (NB / 32) / 256, 256>>>();           // 8192 blocks
    finalize_kernel<<<1, 32>>>((float*)d_out);
}

// round 4
// speedup vs baseline: 7.6737x; 7.6737x over previous
#include <cuda_runtime.h>
#include <cuda_bf16.h>
#include <cstdint>

#define NB 8192
#define ND 1024
#define NC 256
#define MARGIN 0.2f
#define THRESH 0.5f
#define NWORD (NB / 32)

#define BM 128
#define BN 128
#define BK 64
#define STAGES 3
#define STAGE_BYTES 32768          // A tile 16 KB + B tile 16 KB
#define B_OFF 16384
#define SWZ(o) ((o) ^ (((o) >> 3) & 0x70))   // SW128: bits[6:4] ^= bits[9:7]

// ---------------- device scratch ----------------
__device__ __align__(16) __nv_bfloat16 g_imgh[(size_t)NB * ND];
__device__ __align__(16) __nv_bfloat16 g_txth[(size_t)NB * ND];
__device__ __align__(16) __nv_bfloat16 g_labh[(size_t)NB * NC];
__device__ __align__(16) __nv_bfloat16 g_sim[(size_t)NB * NB];   // 128 MB
__device__ unsigned g_posbits[(size_t)NB * NWORD];               // fully overwritten each run
__device__ unsigned g_rowmax[NB];
__device__ unsigned g_rowflags[NB];
__device__ double   g_sum;
__device__ unsigned g_cnt;

// monotone encode/decode: unsigned atomicMax == float max
__device__ __forceinline__ unsigned encf(float f) {
    unsigned u = __float_as_uint(f);
    return (u & 0x80000000u) ? ~u : (u | 0x80000000u);
}
__device__ __forceinline__ float decf(unsigned u) {
    u = (u & 0x80000000u) ? (u & 0x7fffffffu) : ~u;
    return __uint_as_float(u);
}
__device__ __forceinline__ uint32_t smem_u32(const void* p) {
    uint32_t a;
    asm("{ .reg .u64 t; cvta.to.shared.u64 t, %1; cvt.u32.u64 %0, t; }" : "=r"(a) : "l"(p));
    return a;
}
__device__ __forceinline__ void cp16(uint32_t dst, const void* src) {
    asm volatile("cp.async.cg.shared.global [%0], [%1], 16;" :: "r"(dst), "l"(src));
}
#define CP_COMMIT() asm volatile("cp.async.commit_group;" ::: "memory")
#define CP_WAIT(n)  asm volatile("cp.async.wait_group %0;" :: "n"(n) : "memory")

__device__ __forceinline__ void ldsm4(uint32_t addr, uint32_t r[4]) {
    asm volatile("ldmatrix.sync.aligned.m8n8.x4.shared.b16 {%0,%1,%2,%3}, [%4];"
                 : "=r"(r[0]), "=r"(r[1]), "=r"(r[2]), "=r"(r[3]) : "r"(addr));
}
__device__ __forceinline__ void mma16816(float d[4], const uint32_t a[4],
                                         uint32_t b0, uint32_t b1) {
    asm volatile("mma.sync.aligned.m16n8k16.row.col.f32.bf16.bf16.f32 "
                 "{%0,%1,%2,%3}, {%4,%5,%6,%7}, {%8,%9}, {%0,%1,%2,%3};"
                 : "+f"(d[0]), "+f"(d[1]), "+f"(d[2]), "+f"(d[3])
                 : "r"(a[0]), "r"(a[1]), "r"(a[2]), "r"(a[3]), "r"(b0), "r"(b1));
}

// ---------------- stage load: A[128x64] + B[128x64] bf16, SW128 swizzled ----------------
__device__ __forceinline__ void load_stage(const __nv_bfloat16* __restrict__ Ag,
                                           const __nv_bfloat16* __restrict__ Bg,
                                           int K, int ti, int tj, int k0,
                                           uint32_t sbase, int tid) {
#pragma unroll
    for (int u = 0; u < 4; u++) {
        int ch = u * 256 + tid, row = ch >> 3, cc = ch & 7;
        cp16(sbase + SWZ((uint32_t)(row * 128 + cc * 16)),
             (const char*)(Ag + (size_t)(ti + row) * K + k0) + cc * 16);
    }
#pragma unroll
    for (int u = 0; u < 4; u++) {
        int ch = u * 256 + tid, row = ch >> 3, cc = ch & 7;
        cp16(sbase + B_OFF + SWZ((uint32_t)(row * 128 + cc * 16)),
             (const char*)(Bg + (size_t)(tj + row) * K + k0) + cc * 16);
    }
}

// ---------------- compute one 64-wide K stage: warp tile 32x64, 2x8 mma grid ----------------
__device__ __forceinline__ void compute_stage(uint32_t sA, uint32_t sB, int lane,
                                              int wy, int wx, float acc[2][8][4]) {
    const int wr0 = wy * 32, wc0 = wx * 64;
#pragma unroll
    for (int kk = 0; kk < 4; kk++) {
        uint32_t af[2][4];
#pragma unroll
        for (int mt = 0; mt < 2; mt++) {
            int row = wr0 + mt * 16 + (lane & 15);
            int byt = kk * 32 + (lane >> 4) * 16;
            ldsm4(sA + SWZ((uint32_t)(row * 128 + byt)), af[mt]);
        }
        uint32_t bf[4][4];
#pragma unroll
        for (int p = 0; p < 4; p++) {
            int n   = wc0 + p * 16 + (lane >> 4) * 8 + (lane & 7);
            int byt = kk * 32 + ((lane >> 3) & 1) * 16;
            ldsm4(sB + SWZ((uint32_t)(n * 128 + byt)), bf[p]);
        }
#pragma unroll
        for (int mt = 0; mt < 2; mt++)
#pragma unroll
            for (int p = 0; p < 4; p++) {
                mma16816(acc[mt][2 * p],     af[mt], bf[p][0], bf[p][1]);
                mma16816(acc[mt][2 * p + 1], af[mt], bf[p][2], bf[p][3]);
            }
    }
}

// ---------------- pipelined GEMM: acc += A[ti:,:] @ B[tj:,:]^T over K ----------------
template <int K>
__device__ __forceinline__ void gemm(const __nv_bfloat16* __restrict__ Ag,
                                     const __nv_bfloat16* __restrict__ Bg,
                                     int ti, int tj, uint32_t su,
                                     int tid, int lane, int wy, int wx,
                                     float acc[2][8][4]) {
    constexpr int NS = K / BK;
#pragma unroll
    for (int s = 0; s < STAGES - 1; s++) {
        load_stage(Ag, Bg, K, ti, tj, s * BK, su + s * STAGE_BYTES, tid);
        CP_COMMIT();
    }
#pragma unroll 1
    for (int ks = 0; ks < NS; ks++) {
        CP_WAIT(STAGES - 2);
        __syncthreads();
        int nx = ks + STAGES - 1;
        if (nx < NS)
            load_stage(Ag, Bg, K, ti, tj, nx * BK, su + (nx % STAGES) * STAGE_BYTES, tid);
        CP_COMMIT();
        uint32_t sb = su + (ks % STAGES) * STAGE_BYTES;
        compute_stage(sb, sb + B_OFF, lane, wy, wx, acc);
    }
    CP_WAIT(0);
    __syncthreads();
}

// ---------------- fused tile kernel ----------------
__global__ __launch_bounds__(256, 2) void tile_kernel() {
    extern __shared__ char smem[];
    uint32_t su = smem_u32(smem);
    const int tid = threadIdx.x, lane = tid & 31, wid = tid >> 5;
    const int wy = wid & 3, wx = wid >> 2;       // 4 row-groups x 2 col-groups
    const int ti = blockIdx.y * BM, tj = blockIdx.x * BN;
    const int q = lane & 3, g = lane >> 2;

    float acc[2][8][4];
#pragma unroll
    for (int a = 0; a < 2; a++)
#pragma unroll
        for (int b = 0; b < 8; b++)
#pragma unroll
            for (int c = 0; c < 4; c++) acc[a][b][c] = 0.f;

    // ---- gram = lab @ lab^T (K=256) ----
    gemm<NC>(g_labh, g_labh, ti, tj, su, tid, lane, wy, wx, acc);

    unsigned negbits[4];   // per local row rr: own 16 col bits (nt*2+j)
#pragma unroll
    for (int rr = 0; rr < 4; rr++) {
        const int mt = rr >> 1, hf = rr & 1;
        const int grow = ti + wy * 32 + mt * 16 + hf * 8 + g;
        unsigned pw0 = 0, pw1 = 0, nw0 = 0, nw1 = 0, own = 0;
#pragma unroll
        for (int nt = 0; nt < 8; nt++) {
#pragma unroll
            for (int j = 0; j < 2; j++) {
                float v = acc[mt][nt][hf * 2 + j];
                int col = nt * 8 + q * 2 + j;           // 0..63 within warp cols
                int gj = tj + wx * 64 + col;
                bool dg = (grow == gj);
                bool pos = (v > THRESH) && !dg;
                bool neg = !pos && !dg;
                unsigned bit = 1u << (col & 31);
                if (col < 32) { if (pos) pw0 |= bit; if (neg) nw0 |= bit; }
                else          { if (pos) pw1 |= bit; if (neg) nw1 |= bit; }
                if (neg) own |= 1u << (nt * 2 + j);
            }
        }
        negbits[rr] = own;
        pw0 |= __shfl_xor_sync(~0u, pw0, 1); pw0 |= __shfl_xor_sync(~0u, pw0, 2);
        pw1 |= __shfl_xor_sync(~0u, pw1, 1); pw1 |= __shfl_xor_sync(~0u, pw1, 2);
        nw0 |= __shfl_xor_sync(~0u, nw0, 1); nw0 |= __shfl_xor_sync(~0u, nw0, 2);
        nw1 |= __shfl_xor_sync(~0u, nw1, 1); nw1 |= __shfl_xor_sync(~0u, nw1, 2);
        if (q == 0) {
            size_t base = (size_t)grow * NWORD + (size_t)((tj + wx * 64) >> 5);
            g_posbits[base] = pw0;
            g_posbits[base + 1] = pw1;
            unsigned fl = ((pw0 | pw1) ? 1u : 0u) | ((nw0 | nw1) ? 2u : 0u);
            if (fl) atomicOr(&g_rowflags[grow], fl);
        }
    }

    // ---- sim = img @ txt^T (K=1024) ----
#pragma unroll
    for (int a = 0; a < 2; a++)
#pragma unroll
        for (int b = 0; b < 8; b++)
#pragma unroll
            for (int c = 0; c < 4; c++) acc[a][b][c] = 0.f;
    gemm<ND>(g_imgh, g_txth, ti, tj, su, tid, lane, wy, wx, acc);

#pragma unroll
    for (int rr = 0; rr < 4; rr++) {
        const int mt = rr >> 1, hf = rr & 1;
        const int grow = ti + wy * 32 + mt * 16 + hf * 8 + g;
        const unsigned own = negbits[rr];
        float mx = __int_as_float(0xff800000);   // -inf
        __nv_bfloat162* dst = reinterpret_cast<__nv_bfloat162*>(
            g_sim + (size_t)grow * NB + tj + wx * 64 + q * 2);
#pragma unroll
        for (int nt = 0; nt < 8; nt++) {
            float v0 = acc[mt][nt][hf * 2], v1 = acc[mt][nt][hf * 2 + 1];
            dst[nt * 4] = __floats2bfloat162_rn(v0, v1);
            if (own & (1u << (nt * 2)))     mx = fmaxf(mx, v0);
            if (own & (1u << (nt * 2 + 1))) mx = fmaxf(mx, v1);
        }
        mx = fmaxf(mx, __shfl_xor_sync(~0u, mx, 1));
        mx = fmaxf(mx, __shfl_xor_sync(~0u, mx, 2));
        if (q == 0) atomicMax(&g_rowmax[grow], encf(mx));
    }
}

// ---------------- fp32 -> bf16 conversion ----------------
__global__ void cvt_kernel(const float* __restrict__ src, int which, int n8) {
    int i = blockIdx.x * 256 + threadIdx.x;
    if (i >= n8) return;
    __nv_bfloat16* dst = (which == 0) ? g_imgh : (which == 1) ? g_txth : g_labh;
    float4 a = reinterpret_cast<const float4*>(src)[2 * i];
    float4 b = reinterpret_cast<const float4*>(src)[2 * i + 1];
    union { uint4 v; __nv_bfloat162 h[4]; } pk;
    pk.h[0] = __floats2bfloat162_rn(a.x, a.y);
    pk.h[1] = __floats2bfloat162_rn(a.z, a.w);
    pk.h[2] = __floats2bfloat162_rn(b.x, b.y);
    pk.h[3] = __floats2bfloat162_rn(b.z, b.w);
    reinterpret_cast<uint4*>(dst)[i] = pk.v;
}

// ---------------- reset ----------------
__global__ void reset_kernel() {
    int i = blockIdx.x * 256 + threadIdx.x;
    if (i < NB) { g_rowmax[i] = 0x007fffffu; g_rowflags[i] = 0u; }   // encf(-inf)
    if (i == 0) { g_sum = 0.0; g_cnt = 0u; }
}

// ---------------- pass 2: hinge sum over positive pairs ----------------
__global__ void pass2_kernel() {
    int w = blockIdx.x * 256 + threadIdx.x;
    double lsum = 0.0;
    unsigned lcnt = 0u;
    int i = w >> 8;
    int jb = (w & 255) << 5;
    if (g_rowflags[i] == 3u) {
        unsigned m = g_posbits[w];
        if (m) {
            lcnt = (unsigned)__popc(m);
            float base = MARGIN + decf(g_rowmax[i]);
            const __nv_bfloat16* row = g_sim + (size_t)i * NB + jb;
            float fs = 0.f;
            do {
                int b = __ffs(m) - 1; m &= m - 1u;
                float h = base - __bfloat162float(row[b]);
                if (h > 0.f) fs += h;
            } while (m);
            lsum = (double)fs;
        }
    }
#pragma unroll
    for (int off = 16; off; off >>= 1) {
        lsum += __shfl_down_sync(0xffffffffu, lsum, off);
        lcnt += __shfl_down_sync(0xffffffffu, lcnt, off);
    }
    __shared__ double ssum[8];
    __shared__ unsigned scnt[8];
    int lane = threadIdx.x & 31, wid = threadIdx.x >> 5;
    if (lane == 0) { ssum[wid] = lsum; scnt[wid] = lcnt; }
    __syncthreads();
    if (wid == 0) {
        lsum = (lane < 8) ? ssum[lane] : 0.0;
        lcnt = (lane < 8) ? scnt[lane] : 0u;
#pragma unroll
        for (int off = 4; off; off >>= 1) {
            lsum += __shfl_down_sync(0xffffffffu, lsum, off);
            lcnt += __shfl_down_sync(0xffffffffu, lcnt, off);
        }
        if (lane == 0) { atomicAdd(&g_sum, lsum); atomicAdd(&g_cnt, lcnt); }
    }
}

__global__ void finalize_kernel(float* out) {
    if (threadIdx.x == 0)
        out[0] = (g_cnt > 0u) ? (float)(g_sum / (double)g_cnt) : 0.f;
}

// ---------------- launch ----------------
extern "C" void kernel_launch(void* const* d_in, const int* in_sizes, int n_in,
                              void* d_out, int out_size) {
    const float* img = (const float*)d_in[0];
    const float* txt = (const float*)d_in[1];
    const float* lab = (const float*)d_in[2];
    (void)in_sizes; (void)n_in; (void)out_size;

    static int smem_set = 0;
    if (!smem_set) {
        cudaFuncSetAttribute(tile_kernel, cudaFuncAttributeMaxDynamicSharedMemorySize,
                             STAGES * STAGE_BYTES);
        smem_set = 1;
    }

    reset_kernel<<<32, 256>>>();
    cvt_kernel<<<(NB * ND / 8 + 255) / 256, 256>>>(img, 0, NB * ND / 8);
    cvt_kernel<<<(NB * ND / 8 + 255) / 256, 256>>>(txt, 1, NB * ND / 8);
    cvt_kernel<<<(NB * NC / 8 + 255) / 256, 256>>>(lab, 2, NB * NC / 8);

    dim3 grid(NB / BN, NB / BM);   // 64 x 64
    tile_kernel<<<grid, 256, STAGES * STAGE_BYTES>>>();

    pass2_kernel<<<NB * NWORD / 256, 256>>>();
    finalize_kernel<<<1, 32>>>((float*)d_out);
}